// round 8
// baseline (speedup 1.0000x reference)
#include <cuda_runtime.h>
#include <cuda_fp16.h>
#include <mma.h>
#include <math.h>
#include <stdint.h>

using namespace nvcuda;

#define N_MAX 100000
#define E_MAX 1600000

// ---------------- device scratch (static, no allocation) ----------------
__device__ int    g_deg[N_MAX];
__device__ int    g_cursor[N_MAX];
__device__ int    g_rowstart[N_MAX];
__device__ int    g_total;
__device__ int    g_ebuf[E_MAX];
__device__ __align__(16) __half g_y1h[N_MAX * 64]; // fp16(x @ W_l1)
__device__ __align__(16) float  g_r1[N_MAX * 64];  // x @ W_r1 + b_l1
__device__ __align__(16) __half g_hid[N_MAX * 64]; // fp16(relu(mean + root))
__device__ __align__(16) __half g_y2h[N_MAX * 40]; // fp16(hid @ W_l2)
__device__ __align__(16) float  g_r2[N_MAX * 40];  // hid @ W_r2 + b_l2

// ---------------- CSR build (order-free segments) ----------------
__global__ void count_deg_kernel(const int* __restrict__ dst, int e) {
    int i = blockIdx.x * blockDim.x + threadIdx.x;
    if (i == 0) g_total = 0;  // consumed only by assign_kernel (stream-ordered after)
    if (i < e) atomicAdd(&g_deg[dst[i]], 1);
}

__global__ void assign_kernel(int n) {
    __shared__ int wsum[32];
    __shared__ int blockbase;
    int t = threadIdx.x;
    int i = blockIdx.x * blockDim.x + t;
    int v = (i < n) ? g_deg[i] : 0;
    int x = v;
#pragma unroll
    for (int o = 1; o < 32; o <<= 1) {
        int u = __shfl_up_sync(0xffffffffu, x, o);
        if ((t & 31) >= o) x += u;
    }
    if ((t & 31) == 31) wsum[t >> 5] = x;
    __syncthreads();
    if (t < 32) {
        int w = (t < 8) ? wsum[t] : 0;
#pragma unroll
        for (int o = 1; o < 8; o <<= 1) {
            int u = __shfl_up_sync(0xffffffffu, w, o);
            if (t >= o) w += u;
        }
        if (t == 7) blockbase = atomicAdd(&g_total, w);
        wsum[t] = w;
    }
    __syncthreads();
    int base = blockbase + ((t >= 32) ? wsum[(t >> 5) - 1] : 0);
    if (i < n) {
        int rs = base + x - v;
        g_rowstart[i] = rs;
        g_cursor[i] = rs;
    }
}

__global__ void fill_csr_kernel(const int* __restrict__ src,
                                const int* __restrict__ dst, int e) {
    int i = blockIdx.x * blockDim.x + threadIdx.x;
    if (i < e) {
        int pos = atomicAdd(&g_cursor[dst[i]], 1);
        g_ebuf[pos] = src[i];
    }
}

// ------- layer-1 HMMA, N-split: grid.y=0 -> y1h (Wl), grid.y=1 -> r1 (Wr)+bias
// block 256 thr / 8 warps; warp tile 16 rows x 64 cols; smem A[128][136]h + B[128][72]h
#define LDA1 136
#define LDB1 72
#define LDC1 68
__global__ __launch_bounds__(256) void gemm1_kernel(
    const float* __restrict__ x, const float* __restrict__ Wl,
    const float* __restrict__ Wr, const float* __restrict__ bl, int n) {
    extern __shared__ char smem[];
    __half* As = (__half*)smem;                        // 34816 B
    __half* Bs = (__half*)(smem + 128 * LDA1 * 2);     // 18432 B
    float*  Cs = (float*)smem;                         // [128][68] alias over As
    int tid = threadIdx.x;
    int node0 = blockIdx.x * 128;
    int half_sel = blockIdx.y;
    const float* W = half_sel ? Wr : Wl;

    for (int i = tid; i < 128 * 32; i += 256) {
        int row = i >> 5, c4 = i & 31;
        int gr = node0 + row;
        float4 v = (gr < n) ? ((const float4*)x)[gr * 32 + c4]
                            : make_float4(0.f, 0.f, 0.f, 0.f);
        *(__half2*)&As[row * LDA1 + c4 * 4] = __floats2half2_rn(v.x, v.y);
        *(__half2*)&As[row * LDA1 + c4 * 4 + 2] = __floats2half2_rn(v.z, v.w);
    }
    for (int i = tid; i < 128 * 64; i += 256) {
        int k = i >> 6, c = i & 63;
        Bs[k * LDB1 + c] = __float2half_rn(W[k * 64 + c]);
    }
    __syncthreads();

    int wid = tid >> 5;
    int wr = wid * 16;
    wmma::fragment<wmma::accumulator, 16, 16, 16, float> acc[4];
#pragma unroll
    for (int j = 0; j < 4; j++) wmma::fill_fragment(acc[j], 0.f);

#pragma unroll
    for (int k = 0; k < 128; k += 16) {
        wmma::fragment<wmma::matrix_a, 16, 16, 16, __half, wmma::row_major> af;
        wmma::load_matrix_sync(af, &As[wr * LDA1 + k], LDA1);
#pragma unroll
        for (int j = 0; j < 4; j++) {
            wmma::fragment<wmma::matrix_b, 16, 16, 16, __half, wmma::row_major> bf;
            wmma::load_matrix_sync(bf, &Bs[k * LDB1 + j * 16], LDB1);
            wmma::mma_sync(acc[j], af, bf, acc[j]);
        }
    }
    __syncthreads();
#pragma unroll
    for (int j = 0; j < 4; j++)
        wmma::store_matrix_sync(&Cs[wr * LDC1 + j * 16], acc[j], LDC1,
                                wmma::mem_row_major);
    __syncthreads();

    int row = tid >> 1, cb = (tid & 1) * 32;
    int m = node0 + row;
    if (m < n) {
        const float* c = &Cs[row * LDC1 + cb];
        if (half_sel == 0) {
            uint32_t* dst = (uint32_t*)&g_y1h[m * 64 + cb];
#pragma unroll
            for (int j = 0; j < 32; j += 2) {
                __half2 h = __floats2half2_rn(c[j], c[j + 1]);
                dst[j >> 1] = *reinterpret_cast<uint32_t*>(&h);
            }
        } else {
            float4* dst = (float4*)&g_r1[m * 64 + cb];
#pragma unroll
            for (int j = 0; j < 32; j += 4)
                dst[j >> 2] = make_float4(c[j] + bl[cb + j], c[j + 1] + bl[cb + j + 1],
                                          c[j + 2] + bl[cb + j + 2], c[j + 3] + bl[cb + j + 3]);
        }
    }
}

// ------- combine layer 1: hid = fp16(relu(gather_mean(y1) + r1)), MLP 8 --
__global__ void combine1_kernel(int n) {
    int node = (blockIdx.x * blockDim.x + threadIdx.x) >> 5;
    int lane = threadIdx.x & 31;
    if (node >= n) return;
    int s = g_rowstart[node];
    int dg = g_deg[node];
    int e = s + dg;
    float inv = 1.f / (float)max(dg, 1);
    const __half2* y1 = (const __half2*)g_y1h;
    float p0[8], p1[8];
#pragma unroll
    for (int j = 0; j < 8; j++) { p0[j] = 0.f; p1[j] = 0.f; }
    for (int base = s; base < e; base += 32) {
        int cnt = min(32, e - base);
        int idx = (lane < cnt) ? g_ebuf[base + lane] : 0;
        int j = 0;
        for (; j + 8 <= cnt; j += 8) {
            int nn[8];
#pragma unroll
            for (int q = 0; q < 8; q++) nn[q] = __shfl_sync(0xffffffffu, idx, j + q);
#pragma unroll
            for (int q = 0; q < 8; q++) {
                float2 v = __half22float2(y1[nn[q] * 32 + lane]);
                p0[q] += v.x; p1[q] += v.y;
            }
        }
        for (; j < cnt; j++) {
            int n0 = __shfl_sync(0xffffffffu, idx, j);
            float2 v = __half22float2(y1[n0 * 32 + lane]);
            p0[0] += v.x; p1[0] += v.y;
        }
    }
    float a0 = (p0[0] + p0[1]) + (p0[2] + p0[3]) + ((p0[4] + p0[5]) + (p0[6] + p0[7]));
    float a1 = (p1[0] + p1[1]) + (p1[2] + p1[3]) + ((p1[4] + p1[5]) + (p1[6] + p1[7]));
    float2 r = *(const float2*)&g_r1[node * 64 + lane * 2];
    float h0 = fmaxf(a0 * inv + r.x, 0.f);
    float h1 = fmaxf(a1 * inv + r.y, 0.f);
    *(__half2*)&g_hid[node * 64 + lane * 2] = __floats2half2_rn(h0, h1);
}

// ------- layer-2 HMMA, N-split: grid.y=0 -> y2h (Wl2), y=1 -> r2 (Wr2)+bias
// block 256 thr / 8 warps; warp tile 16 rows x 48 cols (40 used)
#define LDA2 72
#define LDB2 56
#define LDC2 56
__global__ __launch_bounds__(256) void gemm2_kernel(
    const float* __restrict__ Wl, const float* __restrict__ Wr,
    const float* __restrict__ bl, int n) {
    extern __shared__ char smem[];
    __half* As = (__half*)smem;                        // [128][72] = 18432 B
    __half* Bs = (__half*)(smem + 128 * LDA2 * 2);     // [64][56]  = 7168 B
    float*  Cs = (float*)smem;                         // [128][56] = 28672 B alias
    int tid = threadIdx.x;
    int node0 = blockIdx.x * 128;
    int half_sel = blockIdx.y;
    const float* W = half_sel ? Wr : Wl;

    for (int i = tid; i < 128 * 8; i += 256) {
        int row = i >> 3, c8 = i & 7;
        int gr = node0 + row;
        uint4 v = (gr < n) ? ((const uint4*)g_hid)[gr * 8 + c8] : make_uint4(0, 0, 0, 0);
        *(uint4*)&As[row * LDA2 + c8 * 8] = v;
    }
    for (int i = tid; i < 64 * 48; i += 256) {
        int k = i / 48, c = i % 48;
        Bs[k * LDB2 + c] = (c < 40) ? __float2half_rn(W[k * 40 + c]) : __half(0.f);
    }
    __syncthreads();

    int wid = tid >> 5;
    int wr = wid * 16;
    wmma::fragment<wmma::accumulator, 16, 16, 16, float> acc[3];
#pragma unroll
    for (int j = 0; j < 3; j++) wmma::fill_fragment(acc[j], 0.f);
#pragma unroll
    for (int k = 0; k < 64; k += 16) {
        wmma::fragment<wmma::matrix_a, 16, 16, 16, __half, wmma::row_major> af;
        wmma::load_matrix_sync(af, &As[wr * LDA2 + k], LDA2);
#pragma unroll
        for (int j = 0; j < 3; j++) {
            wmma::fragment<wmma::matrix_b, 16, 16, 16, __half, wmma::row_major> bf;
            wmma::load_matrix_sync(bf, &Bs[k * LDB2 + j * 16], LDB2);
            wmma::mma_sync(acc[j], af, bf, acc[j]);
        }
    }
    __syncthreads();
#pragma unroll
    for (int j = 0; j < 3; j++)
        wmma::store_matrix_sync(&Cs[wr * LDC2 + j * 16], acc[j], LDC2,
                                wmma::mem_row_major);
    __syncthreads();

    int row = tid >> 1, cb = (tid & 1) * 20;
    int m = node0 + row;
    if (m < n) {
        const float* c = &Cs[row * LDC2 + cb];
        if (half_sel == 0) {
            uint32_t* dst = (uint32_t*)&g_y2h[m * 40 + cb];
#pragma unroll
            for (int j = 0; j < 20; j += 2) {
                __half2 h = __floats2half2_rn(c[j], c[j + 1]);
                dst[j >> 1] = *reinterpret_cast<uint32_t*>(&h);
            }
        } else {
            float4* dst = (float4*)&g_r2[m * 40 + cb];
#pragma unroll
            for (int j = 0; j < 20; j += 4)
                dst[j >> 2] = make_float4(c[j] + bl[cb + j], c[j + 1] + bl[cb + j + 1],
                                          c[j + 2] + bl[cb + j + 2], c[j + 3] + bl[cb + j + 3]);
        }
    }
}

// ------- combine layer 2: out = log_softmax(gather_mean(y2) + r2), MLP 8 -
__global__ void combine2_kernel(float* __restrict__ out, int n) {
    int node = (blockIdx.x * blockDim.x + threadIdx.x) >> 5;
    int lane = threadIdx.x & 31;
    if (node >= n) return;
    int s = g_rowstart[node];
    int dg = g_deg[node];
    int e = s + dg;
    float inv = 1.f / (float)max(dg, 1);
    const __half2* y2 = (const __half2*)g_y2h;
    bool act = lane < 20;
    float p0[8], p1[8];
#pragma unroll
    for (int j = 0; j < 8; j++) { p0[j] = 0.f; p1[j] = 0.f; }
    for (int base = s; base < e; base += 32) {
        int cnt = min(32, e - base);
        int idx = (lane < cnt) ? g_ebuf[base + lane] : 0;
        int j = 0;
        for (; j + 8 <= cnt; j += 8) {
            int nn[8];
#pragma unroll
            for (int q = 0; q < 8; q++) nn[q] = __shfl_sync(0xffffffffu, idx, j + q);
            if (act) {
#pragma unroll
                for (int q = 0; q < 8; q++) {
                    float2 v = __half22float2(y2[nn[q] * 20 + lane]);
                    p0[q] += v.x; p1[q] += v.y;
                }
            }
        }
        for (; j < cnt; j++) {
            int n0 = __shfl_sync(0xffffffffu, idx, j);
            if (act) {
                float2 v = __half22float2(y2[n0 * 20 + lane]);
                p0[0] += v.x; p1[0] += v.y;
            }
        }
    }
    float a0 = (p0[0] + p0[1]) + (p0[2] + p0[3]) + ((p0[4] + p0[5]) + (p0[6] + p0[7]));
    float a1 = (p1[0] + p1[1]) + (p1[2] + p1[3]) + ((p1[4] + p1[5]) + (p1[6] + p1[7]));
    const float NEG_INF = __int_as_float(0xff800000);
    float v0 = NEG_INF, v1 = NEG_INF;
    if (act) {
        v0 = a0 * inv + g_r2[node * 40 + 2 * lane];
        v1 = a1 * inv + g_r2[node * 40 + 2 * lane + 1];
    }
    float m = fmaxf(v0, v1);
#pragma unroll
    for (int o = 16; o > 0; o >>= 1) m = fmaxf(m, __shfl_xor_sync(0xffffffffu, m, o));
    float sum = act ? (expf(v0 - m) + expf(v1 - m)) : 0.f;
#pragma unroll
    for (int o = 16; o > 0; o >>= 1) sum += __shfl_xor_sync(0xffffffffu, sum, o);
    float lse = logf(sum);
    if (act) {
        out[node * 40 + 2 * lane] = v0 - m - lse;
        out[node * 40 + 2 * lane + 1] = v1 - m - lse;
    }
}

// ---------------- launch ----------------
extern "C" void kernel_launch(void* const* d_in, const int* in_sizes, int n_in,
                              void* d_out, int out_size) {
    const float* x   = (const float*)d_in[0];
    const int*   ei  = (const int*)d_in[1];   // int64 inputs delivered as int32
    const float* Wl1 = (const float*)d_in[2];
    const float* bl1 = (const float*)d_in[3];
    const float* Wr1 = (const float*)d_in[4];
    const float* Wl2 = (const float*)d_in[5];
    const float* bl2 = (const float*)d_in[6];
    const float* Wr2 = (const float*)d_in[7];
    float* out = (float*)d_out;

    int n = in_sizes[0] / 128;
    int e = in_sizes[1] / 2;
    const int* src = ei;
    const int* dst = ei + e;

    const int SMEM1 = 128 * LDA1 * 2 + 128 * LDB1 * 2;   // 53248 B
    const int SMEM2 = 128 * LDC2 * 4;                    // 28672 B
    cudaFuncSetAttribute(gemm1_kernel, cudaFuncAttributeMaxDynamicSharedMemorySize, SMEM1);
    cudaFuncSetAttribute(gemm2_kernel, cudaFuncAttributeMaxDynamicSharedMemorySize, SMEM2);

    void* deg_ptr = nullptr;
    cudaGetSymbolAddress(&deg_ptr, g_deg);

    cudaStream_t s2;
    cudaStreamCreateWithFlags(&s2, cudaStreamNonBlocking);
    cudaEvent_t evFork, evJoin;
    cudaEventCreateWithFlags(&evFork, cudaEventDisableTiming);
    cudaEventCreateWithFlags(&evJoin, cudaEventDisableTiming);

    cudaEventRecord(evFork, 0);
    cudaStreamWaitEvent(s2, evFork, 0);

    cudaMemsetAsync(deg_ptr, 0, (size_t)n * sizeof(int), s2);
    count_deg_kernel<<<(e + 255) / 256, 256, 0, s2>>>(dst, e);
    assign_kernel<<<(n + 255) / 256, 256, 0, s2>>>(n);
    fill_csr_kernel<<<(e + 255) / 256, 256, 0, s2>>>(src, dst, e);
    cudaEventRecord(evJoin, s2);

    int nblk = (n + 127) / 128;
    dim3 g1(nblk, 2);
    gemm1_kernel<<<g1, 256, SMEM1>>>(x, Wl1, Wr1, bl1, n);

    cudaStreamWaitEvent(0, evJoin, 0);
    combine1_kernel<<<(n * 32 + 255) / 256, 256>>>(n);
    dim3 g2(nblk, 2);
    gemm2_kernel<<<g2, 256, SMEM2>>>(Wl2, Wr2, bl2, n);
    combine2_kernel<<<(n * 32 + 255) / 256, 256>>>(out, n);
}

// round 9
// speedup vs baseline: 1.2189x; 1.2189x over previous
#include <cuda_runtime.h>
#include <cuda_fp16.h>
#include <mma.h>
#include <math.h>
#include <stdint.h>

using namespace nvcuda;

#define N_MAX 100000
#define E_MAX 1600000

// ---------------- device scratch (static, no allocation) ----------------
__device__ int    g_deg[N_MAX];
__device__ int    g_cursor[N_MAX];
__device__ int    g_rowstart[N_MAX];
__device__ int    g_total;
__device__ int    g_ebuf[E_MAX];
__device__ __align__(16) __half g_y1h[N_MAX * 64]; // fp16(x @ W_l1)
__device__ __align__(16) float  g_r1[N_MAX * 64];  // x @ W_r1 + b_l1
__device__ __align__(16) __half g_hid[N_MAX * 64]; // fp16(relu(mean + root))
__device__ __align__(16) __half g_y2h[N_MAX * 40]; // fp16(hid @ W_l2)
__device__ __align__(16) float  g_r2[N_MAX * 40];  // hid @ W_r2 + b_l2

// ---------------- CSR build (order-free segments) ----------------
__global__ void count_deg_kernel(const int* __restrict__ dst, int e) {
    int i = blockIdx.x * blockDim.x + threadIdx.x;
    if (i == 0) g_total = 0;  // consumed only by assign_kernel (stream-ordered after)
    if (i < e) atomicAdd(&g_deg[dst[i]], 1);
}

__global__ void assign_kernel(int n) {
    __shared__ int wsum[32];
    __shared__ int blockbase;
    int t = threadIdx.x;
    int i = blockIdx.x * blockDim.x + t;
    int v = (i < n) ? g_deg[i] : 0;
    int x = v;
#pragma unroll
    for (int o = 1; o < 32; o <<= 1) {
        int u = __shfl_up_sync(0xffffffffu, x, o);
        if ((t & 31) >= o) x += u;
    }
    if ((t & 31) == 31) wsum[t >> 5] = x;
    __syncthreads();
    if (t < 32) {
        int w = (t < 8) ? wsum[t] : 0;
#pragma unroll
        for (int o = 1; o < 8; o <<= 1) {
            int u = __shfl_up_sync(0xffffffffu, w, o);
            if (t >= o) w += u;
        }
        if (t == 7) blockbase = atomicAdd(&g_total, w);
        wsum[t] = w;
    }
    __syncthreads();
    int base = blockbase + ((t >= 32) ? wsum[(t >> 5) - 1] : 0);
    if (i < n) {
        int rs = base + x - v;
        g_rowstart[i] = rs;
        g_cursor[i] = rs;
    }
}

__global__ void fill_csr_kernel(const int* __restrict__ src,
                                const int* __restrict__ dst, int e) {
    int i = blockIdx.x * blockDim.x + threadIdx.x;
    if (i < e) {
        int pos = atomicAdd(&g_cursor[dst[i]], 1);
        g_ebuf[pos] = src[i];
    }
}

// ------- layer-1 HMMA, N-split: grid.y=0 -> y1h (Wl), grid.y=1 -> r1 (Wr)+bias
#define LDA1 136
#define LDB1 72
#define LDC1 68
__global__ __launch_bounds__(256) void gemm1_kernel(
    const float* __restrict__ x, const float* __restrict__ Wl,
    const float* __restrict__ Wr, const float* __restrict__ bl, int n) {
    extern __shared__ char smem[];
    __half* As = (__half*)smem;                        // 34816 B
    __half* Bs = (__half*)(smem + 128 * LDA1 * 2);     // 18432 B
    float*  Cs = (float*)smem;                         // [128][68] alias over As
    int tid = threadIdx.x;
    int node0 = blockIdx.x * 128;
    int half_sel = blockIdx.y;
    const float* W = half_sel ? Wr : Wl;

    for (int i = tid; i < 128 * 32; i += 256) {
        int row = i >> 5, c4 = i & 31;
        int gr = node0 + row;
        float4 v = (gr < n) ? ((const float4*)x)[gr * 32 + c4]
                            : make_float4(0.f, 0.f, 0.f, 0.f);
        *(__half2*)&As[row * LDA1 + c4 * 4] = __floats2half2_rn(v.x, v.y);
        *(__half2*)&As[row * LDA1 + c4 * 4 + 2] = __floats2half2_rn(v.z, v.w);
    }
    for (int i = tid; i < 128 * 64; i += 256) {
        int k = i >> 6, c = i & 63;
        Bs[k * LDB1 + c] = __float2half_rn(W[k * 64 + c]);
    }
    __syncthreads();

    int wid = tid >> 5;
    int wr = wid * 16;
    wmma::fragment<wmma::accumulator, 16, 16, 16, float> acc[4];
#pragma unroll
    for (int j = 0; j < 4; j++) wmma::fill_fragment(acc[j], 0.f);

#pragma unroll
    for (int k = 0; k < 128; k += 16) {
        wmma::fragment<wmma::matrix_a, 16, 16, 16, __half, wmma::row_major> af;
        wmma::load_matrix_sync(af, &As[wr * LDA1 + k], LDA1);
#pragma unroll
        for (int j = 0; j < 4; j++) {
            wmma::fragment<wmma::matrix_b, 16, 16, 16, __half, wmma::row_major> bf;
            wmma::load_matrix_sync(bf, &Bs[k * LDB1 + j * 16], LDB1);
            wmma::mma_sync(acc[j], af, bf, acc[j]);
        }
    }
    __syncthreads();
#pragma unroll
    for (int j = 0; j < 4; j++)
        wmma::store_matrix_sync(&Cs[wr * LDC1 + j * 16], acc[j], LDC1,
                                wmma::mem_row_major);
    __syncthreads();

    // chunk-linear vectorized epilogue: warp-wide stores are contiguous 512B
    if (half_sel == 0) {
        // y1h: 128 rows x 8 uint4 chunks (16B = 8 half)
        for (int c = tid; c < 1024; c += 256) {
            int row = c >> 3, ci = c & 7;
            int m = node0 + row;
            if (m < n) {
                const float* cp = &Cs[row * LDC1 + ci * 8];
                __half2 h0 = __floats2half2_rn(cp[0], cp[1]);
                __half2 h1 = __floats2half2_rn(cp[2], cp[3]);
                __half2 h2 = __floats2half2_rn(cp[4], cp[5]);
                __half2 h3 = __floats2half2_rn(cp[6], cp[7]);
                uint4 u;
                u.x = *reinterpret_cast<uint32_t*>(&h0);
                u.y = *reinterpret_cast<uint32_t*>(&h1);
                u.z = *reinterpret_cast<uint32_t*>(&h2);
                u.w = *reinterpret_cast<uint32_t*>(&h3);
                ((uint4*)(g_y1h + (size_t)m * 64))[ci] = u;
            }
        }
    } else {
        // r1: 128 rows x 16 float4 chunks (+bias)
        for (int c = tid; c < 2048; c += 256) {
            int row = c >> 4, ci = c & 15;
            int m = node0 + row;
            if (m < n) {
                const float* cp = &Cs[row * LDC1 + ci * 4];
                float4 v = make_float4(cp[0] + bl[ci * 4], cp[1] + bl[ci * 4 + 1],
                                       cp[2] + bl[ci * 4 + 2], cp[3] + bl[ci * 4 + 3]);
                ((float4*)(g_r1 + (size_t)m * 64))[ci] = v;
            }
        }
    }
}

// ------- combine layer 1: hid = fp16(relu(gather_mean(y1) + r1)), MLP 4 --
__global__ void combine1_kernel(int n) {
    int node = (blockIdx.x * blockDim.x + threadIdx.x) >> 5;
    int lane = threadIdx.x & 31;
    if (node >= n) return;
    int s = g_rowstart[node];
    int dg = g_deg[node];
    int e = s + dg;
    float inv = 1.f / (float)max(dg, 1);
    const __half2* y1 = (const __half2*)g_y1h;
    float a0 = 0.f, a1 = 0.f, b0 = 0.f, b1 = 0.f;
    float c0 = 0.f, c1 = 0.f, d0 = 0.f, d1 = 0.f;
    for (int base = s; base < e; base += 32) {
        int cnt = min(32, e - base);
        int idx = (lane < cnt) ? g_ebuf[base + lane] : 0;
        int j = 0;
        for (; j + 4 <= cnt; j += 4) {
            int n0 = __shfl_sync(0xffffffffu, idx, j);
            int n1 = __shfl_sync(0xffffffffu, idx, j + 1);
            int n2 = __shfl_sync(0xffffffffu, idx, j + 2);
            int n3 = __shfl_sync(0xffffffffu, idx, j + 3);
            float2 v0 = __half22float2(y1[n0 * 32 + lane]);
            float2 v1 = __half22float2(y1[n1 * 32 + lane]);
            float2 v2 = __half22float2(y1[n2 * 32 + lane]);
            float2 v3 = __half22float2(y1[n3 * 32 + lane]);
            a0 += v0.x; a1 += v0.y;
            b0 += v1.x; b1 += v1.y;
            c0 += v2.x; c1 += v2.y;
            d0 += v3.x; d1 += v3.y;
        }
        for (; j < cnt; j++) {
            int n0 = __shfl_sync(0xffffffffu, idx, j);
            float2 v0 = __half22float2(y1[n0 * 32 + lane]);
            a0 += v0.x; a1 += v0.y;
        }
    }
    a0 += b0 + c0 + d0;
    a1 += b1 + c1 + d1;
    float2 r = *(const float2*)&g_r1[node * 64 + lane * 2];
    float h0 = fmaxf(a0 * inv + r.x, 0.f);
    float h1 = fmaxf(a1 * inv + r.y, 0.f);
    *(__half2*)&g_hid[node * 64 + lane * 2] = __floats2half2_rn(h0, h1);
}

// ------- layer-2 HMMA, N-split: grid.y=0 -> y2h (Wl2), y=1 -> r2 (Wr2)+bias
#define LDA2 72
#define LDB2 56
#define LDC2 56
__global__ __launch_bounds__(256) void gemm2_kernel(
    const float* __restrict__ Wl, const float* __restrict__ Wr,
    const float* __restrict__ bl, int n) {
    extern __shared__ char smem[];
    __half* As = (__half*)smem;                        // [128][72] = 18432 B
    __half* Bs = (__half*)(smem + 128 * LDA2 * 2);     // [64][56]  = 7168 B
    float*  Cs = (float*)smem;                         // [128][56] alias
    int tid = threadIdx.x;
    int node0 = blockIdx.x * 128;
    int half_sel = blockIdx.y;
    const float* W = half_sel ? Wr : Wl;

    for (int i = tid; i < 128 * 8; i += 256) {
        int row = i >> 3, c8 = i & 7;
        int gr = node0 + row;
        uint4 v = (gr < n) ? ((const uint4*)g_hid)[gr * 8 + c8] : make_uint4(0, 0, 0, 0);
        *(uint4*)&As[row * LDA2 + c8 * 8] = v;
    }
    for (int i = tid; i < 64 * 48; i += 256) {
        int k = i / 48, c = i % 48;
        Bs[k * LDB2 + c] = (c < 40) ? __float2half_rn(W[k * 40 + c]) : __half(0.f);
    }
    __syncthreads();

    int wid = tid >> 5;
    int wr = wid * 16;
    wmma::fragment<wmma::accumulator, 16, 16, 16, float> acc[3];
#pragma unroll
    for (int j = 0; j < 3; j++) wmma::fill_fragment(acc[j], 0.f);
#pragma unroll
    for (int k = 0; k < 64; k += 16) {
        wmma::fragment<wmma::matrix_a, 16, 16, 16, __half, wmma::row_major> af;
        wmma::load_matrix_sync(af, &As[wr * LDA2 + k], LDA2);
#pragma unroll
        for (int j = 0; j < 3; j++) {
            wmma::fragment<wmma::matrix_b, 16, 16, 16, __half, wmma::row_major> bf;
            wmma::load_matrix_sync(bf, &Bs[k * LDB2 + j * 16], LDB2);
            wmma::mma_sync(acc[j], af, bf, acc[j]);
        }
    }
    __syncthreads();
#pragma unroll
    for (int j = 0; j < 3; j++)
        wmma::store_matrix_sync(&Cs[wr * LDC2 + j * 16], acc[j], LDC2,
                                wmma::mem_row_major);
    __syncthreads();

    // chunk-linear vectorized epilogue
    if (half_sel == 0) {
        // y2h: 128 rows x 5 uint4 chunks (40 half = 80B, 16B-aligned rows)
        for (int c = tid; c < 640; c += 256) {
            int row = c / 5, ci = c % 5;
            int m = node0 + row;
            if (m < n) {
                const float* cp = &Cs[row * LDC2 + ci * 8];
                __half2 h0 = __floats2half2_rn(cp[0], cp[1]);
                __half2 h1 = __floats2half2_rn(cp[2], cp[3]);
                __half2 h2 = __floats2half2_rn(cp[4], cp[5]);
                __half2 h3 = __floats2half2_rn(cp[6], cp[7]);
                uint4 u;
                u.x = *reinterpret_cast<uint32_t*>(&h0);
                u.y = *reinterpret_cast<uint32_t*>(&h1);
                u.z = *reinterpret_cast<uint32_t*>(&h2);
                u.w = *reinterpret_cast<uint32_t*>(&h3);
                ((uint4*)(g_y2h + (size_t)m * 40))[ci] = u;
            }
        }
    } else {
        // r2: 128 rows x 10 float4 chunks (+bias)
        for (int c = tid; c < 1280; c += 256) {
            int row = c / 10, ci = c % 10;
            int m = node0 + row;
            if (m < n) {
                const float* cp = &Cs[row * LDC2 + ci * 4];
                float4 v = make_float4(cp[0] + bl[ci * 4], cp[1] + bl[ci * 4 + 1],
                                       cp[2] + bl[ci * 4 + 2], cp[3] + bl[ci * 4 + 3]);
                ((float4*)(g_r2 + (size_t)m * 40))[ci] = v;
            }
        }
    }
}

// ------- combine layer 2: out = log_softmax(gather_mean(y2) + r2), MLP 4 -
__global__ void combine2_kernel(float* __restrict__ out, int n) {
    int node = (blockIdx.x * blockDim.x + threadIdx.x) >> 5;
    int lane = threadIdx.x & 31;
    if (node >= n) return;
    int s = g_rowstart[node];
    int dg = g_deg[node];
    int e = s + dg;
    float inv = 1.f / (float)max(dg, 1);
    const __half2* y2 = (const __half2*)g_y2h;
    bool act = lane < 20;
    float a0 = 0.f, a1 = 0.f, b0 = 0.f, b1 = 0.f;
    float c0 = 0.f, c1 = 0.f, d0 = 0.f, d1 = 0.f;
    for (int base = s; base < e; base += 32) {
        int cnt = min(32, e - base);
        int idx = (lane < cnt) ? g_ebuf[base + lane] : 0;
        int j = 0;
        for (; j + 4 <= cnt; j += 4) {
            int n0 = __shfl_sync(0xffffffffu, idx, j);
            int n1 = __shfl_sync(0xffffffffu, idx, j + 1);
            int n2 = __shfl_sync(0xffffffffu, idx, j + 2);
            int n3 = __shfl_sync(0xffffffffu, idx, j + 3);
            if (act) {
                float2 v0 = __half22float2(y2[n0 * 20 + lane]);
                float2 v1 = __half22float2(y2[n1 * 20 + lane]);
                float2 v2 = __half22float2(y2[n2 * 20 + lane]);
                float2 v3 = __half22float2(y2[n3 * 20 + lane]);
                a0 += v0.x; a1 += v0.y;
                b0 += v1.x; b1 += v1.y;
                c0 += v2.x; c1 += v2.y;
                d0 += v3.x; d1 += v3.y;
            }
        }
        for (; j < cnt; j++) {
            int n0 = __shfl_sync(0xffffffffu, idx, j);
            if (act) {
                float2 v0 = __half22float2(y2[n0 * 20 + lane]);
                a0 += v0.x; a1 += v0.y;
            }
        }
    }
    a0 += b0 + c0 + d0;
    a1 += b1 + c1 + d1;
    const float NEG_INF = __int_as_float(0xff800000);
    float v0 = NEG_INF, v1 = NEG_INF;
    if (act) {
        v0 = a0 * inv + g_r2[node * 40 + 2 * lane];
        v1 = a1 * inv + g_r2[node * 40 + 2 * lane + 1];
    }
    float m = fmaxf(v0, v1);
#pragma unroll
    for (int o = 16; o > 0; o >>= 1) m = fmaxf(m, __shfl_xor_sync(0xffffffffu, m, o));
    float sum = act ? (expf(v0 - m) + expf(v1 - m)) : 0.f;
#pragma unroll
    for (int o = 16; o > 0; o >>= 1) sum += __shfl_xor_sync(0xffffffffu, sum, o);
    float lse = logf(sum);
    if (act) {
        out[node * 40 + 2 * lane] = v0 - m - lse;
        out[node * 40 + 2 * lane + 1] = v1 - m - lse;
    }
}

// ---------------- launch ----------------
extern "C" void kernel_launch(void* const* d_in, const int* in_sizes, int n_in,
                              void* d_out, int out_size) {
    const float* x   = (const float*)d_in[0];
    const int*   ei  = (const int*)d_in[1];   // int64 inputs delivered as int32
    const float* Wl1 = (const float*)d_in[2];
    const float* bl1 = (const float*)d_in[3];
    const float* Wr1 = (const float*)d_in[4];
    const float* Wl2 = (const float*)d_in[5];
    const float* bl2 = (const float*)d_in[6];
    const float* Wr2 = (const float*)d_in[7];
    float* out = (float*)d_out;

    int n = in_sizes[0] / 128;
    int e = in_sizes[1] / 2;
    const int* src = ei;
    const int* dst = ei + e;

    const int SMEM1 = 128 * LDA1 * 2 + 128 * LDB1 * 2;   // 53248 B
    const int SMEM2 = 128 * LDC2 * 4;                    // 28672 B
    cudaFuncSetAttribute(gemm1_kernel, cudaFuncAttributeMaxDynamicSharedMemorySize, SMEM1);
    cudaFuncSetAttribute(gemm2_kernel, cudaFuncAttributeMaxDynamicSharedMemorySize, SMEM2);

    void* deg_ptr = nullptr;
    cudaGetSymbolAddress(&deg_ptr, g_deg);

    cudaStream_t s2;
    cudaStreamCreateWithFlags(&s2, cudaStreamNonBlocking);
    cudaEvent_t evFork, evJoin;
    cudaEventCreateWithFlags(&evFork, cudaEventDisableTiming);
    cudaEventCreateWithFlags(&evJoin, cudaEventDisableTiming);

    cudaEventRecord(evFork, 0);
    cudaStreamWaitEvent(s2, evFork, 0);

    cudaMemsetAsync(deg_ptr, 0, (size_t)n * sizeof(int), s2);
    count_deg_kernel<<<(e + 255) / 256, 256, 0, s2>>>(dst, e);
    assign_kernel<<<(n + 255) / 256, 256, 0, s2>>>(n);
    fill_csr_kernel<<<(e + 255) / 256, 256, 0, s2>>>(src, dst, e);
    cudaEventRecord(evJoin, s2);

    int nblk = (n + 127) / 128;
    dim3 g1(nblk, 2);
    gemm1_kernel<<<g1, 256, SMEM1>>>(x, Wl1, Wr1, bl1, n);

    cudaStreamWaitEvent(0, evJoin, 0);
    combine1_kernel<<<(n * 32 + 255) / 256, 256>>>(n);
    dim3 g2(nblk, 2);
    gemm2_kernel<<<g2, 256, SMEM2>>>(Wl2, Wr2, bl2, n);
    combine2_kernel<<<(n * 32 + 255) / 256, 256>>>(out, n);
}

// round 10
// speedup vs baseline: 1.3999x; 1.1485x over previous
#include <cuda_runtime.h>
#include <cuda_fp16.h>
#include <mma.h>
#include <math.h>
#include <stdint.h>

using namespace nvcuda;

#define N_MAX 100000
#define E_MAX 1600000

// ---------------- device scratch (static, no allocation) ----------------
__device__ int    g_deg[N_MAX];
__device__ int    g_cursor[N_MAX];
__device__ int    g_rowstart[N_MAX];
__device__ int    g_total;
__device__ int    g_ebuf[E_MAX];
__device__ __align__(16) __half g_y1h[N_MAX * 64]; // fp16(x @ W_l1)
__device__ __align__(16) float  g_r1[N_MAX * 64];  // x @ W_r1 + b_l1
__device__ __align__(16) __half g_hid[N_MAX * 64]; // fp16(relu(mean + root))
__device__ __align__(16) __half g_y2h[N_MAX * 40]; // fp16(hid @ W_l2)
__device__ __align__(16) float  g_r2[N_MAX * 40];  // hid @ W_r2 + b_l2

// ---------------- CSR build (order-free segments) ----------------
__global__ void count_deg_kernel(const int* __restrict__ dst, int e) {
    int i = blockIdx.x * blockDim.x + threadIdx.x;
    if (i == 0) g_total = 0;  // consumed only by assign_kernel (stream-ordered after)
    if (i < e) atomicAdd(&g_deg[dst[i]], 1);
}

__global__ void assign_kernel(int n) {
    __shared__ int wsum[32];
    __shared__ int blockbase;
    int t = threadIdx.x;
    int i = blockIdx.x * blockDim.x + t;
    int v = (i < n) ? g_deg[i] : 0;
    int x = v;
#pragma unroll
    for (int o = 1; o < 32; o <<= 1) {
        int u = __shfl_up_sync(0xffffffffu, x, o);
        if ((t & 31) >= o) x += u;
    }
    if ((t & 31) == 31) wsum[t >> 5] = x;
    __syncthreads();
    if (t < 32) {
        int w = (t < 8) ? wsum[t] : 0;
#pragma unroll
        for (int o = 1; o < 8; o <<= 1) {
            int u = __shfl_up_sync(0xffffffffu, w, o);
            if (t >= o) w += u;
        }
        if (t == 7) blockbase = atomicAdd(&g_total, w);
        wsum[t] = w;
    }
    __syncthreads();
    int base = blockbase + ((t >= 32) ? wsum[(t >> 5) - 1] : 0);
    if (i < n) {
        int rs = base + x - v;
        g_rowstart[i] = rs;
        g_cursor[i] = rs;
    }
}

__global__ void fill_csr_kernel(const int* __restrict__ src,
                                const int* __restrict__ dst, int e) {
    int i = blockIdx.x * blockDim.x + threadIdx.x;
    if (i < e) {
        int pos = atomicAdd(&g_cursor[dst[i]], 1);
        g_ebuf[pos] = src[i];
    }
}

// ------- layer-1 HMMA, single pass: C[128,128] = x_tile @ [Wl1|Wr1] -----
// 512 threads / 16 warps; warp tile 16 rows x 64 cols (acc[4])
#define LDA1 136
#define LDC1 132
__global__ __launch_bounds__(512) void gemm1_kernel(
    const float* __restrict__ x, const float* __restrict__ Wl,
    const float* __restrict__ Wr, const float* __restrict__ bl, int n) {
    extern __shared__ char smem[];
    __half* As = (__half*)smem;                        // [128][136] = 34816 B
    __half* Bs = (__half*)(smem + 128 * LDA1 * 2);     // [128][136] = 34816 B
    float*  Cs = (float*)smem;                         // [128][132] = 67584 B alias
    int tid = threadIdx.x;
    int node0 = blockIdx.x * 128;

    // A: 128 x 128 fp32 -> fp16 (8 float4 per thread)
    for (int i = tid; i < 128 * 32; i += 512) {
        int row = i >> 5, c4 = i & 31;
        int gr = node0 + row;
        float4 v = (gr < n) ? ((const float4*)x)[gr * 32 + c4]
                            : make_float4(0.f, 0.f, 0.f, 0.f);
        *(__half2*)&As[row * LDA1 + c4 * 4] = __floats2half2_rn(v.x, v.y);
        *(__half2*)&As[row * LDA1 + c4 * 4 + 2] = __floats2half2_rn(v.z, v.w);
    }
    // B: cols 0..63 = Wl1, 64..127 = Wr1, vectorized float4 loads (8/thread)
    for (int i = tid; i < 4096; i += 512) {
        int hs = i >> 11;              // 0 -> Wl, 1 -> Wr
        int f = i & 2047;
        int k = f >> 4, c4 = f & 15;
        float4 v = hs ? ((const float4*)Wr)[f] : ((const float4*)Wl)[f];
        int col = hs * 64 + c4 * 4;
        *(__half2*)&Bs[k * LDA1 + col] = __floats2half2_rn(v.x, v.y);
        *(__half2*)&Bs[k * LDA1 + col + 2] = __floats2half2_rn(v.z, v.w);
    }
    __syncthreads();

    int wid = tid >> 5;
    int wr = (wid & 7) * 16;       // row strip
    int wc = (wid >> 3) * 64;      // col half
    wmma::fragment<wmma::accumulator, 16, 16, 16, float> acc[4];
#pragma unroll
    for (int j = 0; j < 4; j++) wmma::fill_fragment(acc[j], 0.f);

#pragma unroll
    for (int k = 0; k < 128; k += 16) {
        wmma::fragment<wmma::matrix_a, 16, 16, 16, __half, wmma::row_major> af;
        wmma::load_matrix_sync(af, &As[wr * LDA1 + k], LDA1);
#pragma unroll
        for (int j = 0; j < 4; j++) {
            wmma::fragment<wmma::matrix_b, 16, 16, 16, __half, wmma::row_major> bf;
            wmma::load_matrix_sync(bf, &Bs[k * LDA1 + wc + j * 16], LDA1);
            wmma::mma_sync(acc[j], af, bf, acc[j]);
        }
    }
    __syncthreads();
#pragma unroll
    for (int j = 0; j < 4; j++)
        wmma::store_matrix_sync(&Cs[wr * LDC1 + wc + j * 16], acc[j], LDC1,
                                wmma::mem_row_major);
    __syncthreads();

    // coalesced epilogue: y1h (cols 0..63) + r1 (cols 64..127, +bias)
    for (int c = tid; c < 1024; c += 512) {         // 2 chunks/thread
        int row = c >> 3, ci = c & 7;
        int m = node0 + row;
        if (m < n) {
            const float* cp = &Cs[row * LDC1 + ci * 8];
            __half2 h0 = __floats2half2_rn(cp[0], cp[1]);
            __half2 h1 = __floats2half2_rn(cp[2], cp[3]);
            __half2 h2 = __floats2half2_rn(cp[4], cp[5]);
            __half2 h3 = __floats2half2_rn(cp[6], cp[7]);
            uint4 u;
            u.x = *reinterpret_cast<uint32_t*>(&h0);
            u.y = *reinterpret_cast<uint32_t*>(&h1);
            u.z = *reinterpret_cast<uint32_t*>(&h2);
            u.w = *reinterpret_cast<uint32_t*>(&h3);
            ((uint4*)(g_y1h + (size_t)m * 64))[ci] = u;
        }
    }
    for (int c = tid; c < 2048; c += 512) {         // 4 chunks/thread
        int row = c >> 4, ci = c & 15;
        int m = node0 + row;
        if (m < n) {
            const float* cp = &Cs[row * LDC1 + 64 + ci * 4];
            float4 v = make_float4(cp[0] + bl[ci * 4], cp[1] + bl[ci * 4 + 1],
                                   cp[2] + bl[ci * 4 + 2], cp[3] + bl[ci * 4 + 3]);
            ((float4*)(g_r1 + (size_t)m * 64))[ci] = v;
        }
    }
}

// ------- combine layer 1: hid = fp16(relu(gather_mean(y1) + r1)), MLP 4 --
__global__ void combine1_kernel(int n) {
    int node = (blockIdx.x * blockDim.x + threadIdx.x) >> 5;
    int lane = threadIdx.x & 31;
    if (node >= n) return;
    int s = g_rowstart[node];
    int dg = g_deg[node];
    int e = s + dg;
    float inv = 1.f / (float)max(dg, 1);
    const __half2* y1 = (const __half2*)g_y1h;
    float a0 = 0.f, a1 = 0.f, b0 = 0.f, b1 = 0.f;
    float c0 = 0.f, c1 = 0.f, d0 = 0.f, d1 = 0.f;
    for (int base = s; base < e; base += 32) {
        int cnt = min(32, e - base);
        int idx = (lane < cnt) ? g_ebuf[base + lane] : 0;
        int j = 0;
        for (; j + 4 <= cnt; j += 4) {
            int n0 = __shfl_sync(0xffffffffu, idx, j);
            int n1 = __shfl_sync(0xffffffffu, idx, j + 1);
            int n2 = __shfl_sync(0xffffffffu, idx, j + 2);
            int n3 = __shfl_sync(0xffffffffu, idx, j + 3);
            float2 v0 = __half22float2(y1[n0 * 32 + lane]);
            float2 v1 = __half22float2(y1[n1 * 32 + lane]);
            float2 v2 = __half22float2(y1[n2 * 32 + lane]);
            float2 v3 = __half22float2(y1[n3 * 32 + lane]);
            a0 += v0.x; a1 += v0.y;
            b0 += v1.x; b1 += v1.y;
            c0 += v2.x; c1 += v2.y;
            d0 += v3.x; d1 += v3.y;
        }
        for (; j < cnt; j++) {
            int n0 = __shfl_sync(0xffffffffu, idx, j);
            float2 v0 = __half22float2(y1[n0 * 32 + lane]);
            a0 += v0.x; a1 += v0.y;
        }
    }
    a0 += b0 + c0 + d0;
    a1 += b1 + c1 + d1;
    float2 r = *(const float2*)&g_r1[node * 64 + lane * 2];
    float h0 = fmaxf(a0 * inv + r.x, 0.f);
    float h1 = fmaxf(a1 * inv + r.y, 0.f);
    *(__half2*)&g_hid[node * 64 + lane * 2] = __floats2half2_rn(h0, h1);
}

// ------- layer-2 HMMA, single pass: C[128,80] = hid_tile @ [Wl2|Wr2] ----
#define LDA2 72
#define LDB2 88
__global__ __launch_bounds__(256) void gemm2_kernel(
    const float* __restrict__ Wl, const float* __restrict__ Wr,
    const float* __restrict__ bl, int n) {
    extern __shared__ char smem[];
    __half* As = (__half*)smem;                       // [128][72] = 18432 B
    __half* Bs = (__half*)(smem + 128 * LDA2 * 2);    // [64][88]  = 11264 B
    float*  Cs = (float*)smem;                        // [128][88] = 45056 B alias
    int tid = threadIdx.x;
    int node0 = blockIdx.x * 128;

    for (int i = tid; i < 128 * 8; i += 256) {
        int row = i >> 3, c8 = i & 7;
        int gr = node0 + row;
        uint4 v = (gr < n) ? ((const uint4*)g_hid)[gr * 8 + c8] : make_uint4(0, 0, 0, 0);
        *(uint4*)&As[row * LDA2 + c8 * 8] = v;
    }
    // B: cols 0..39 = Wl2, 40..79 = Wr2; vectorized float4 loads (640 each)
    for (int i = tid; i < 1280; i += 256) {
        int hs = i >= 640;
        int f = hs ? i - 640 : i;
        int k = f / 10, c4 = f % 10;
        float4 v = hs ? ((const float4*)Wr)[f] : ((const float4*)Wl)[f];
        int col = hs * 40 + c4 * 4;
        *(__half2*)&Bs[k * LDB2 + col] = __floats2half2_rn(v.x, v.y);
        *(__half2*)&Bs[k * LDB2 + col + 2] = __floats2half2_rn(v.z, v.w);
    }
    // zero pad cols 80..87 so bf loads are clean
    for (int i = tid; i < 64 * 8; i += 256) {
        int k = i >> 3, c = i & 7;
        Bs[k * LDB2 + 80 + c] = __half(0.f);
    }
    __syncthreads();

    int wid = tid >> 5;
    int wr = wid * 16;
    wmma::fragment<wmma::accumulator, 16, 16, 16, float> acc[5];
#pragma unroll
    for (int j = 0; j < 5; j++) wmma::fill_fragment(acc[j], 0.f);
#pragma unroll
    for (int k = 0; k < 64; k += 16) {
        wmma::fragment<wmma::matrix_a, 16, 16, 16, __half, wmma::row_major> af;
        wmma::load_matrix_sync(af, &As[wr * LDA2 + k], LDA2);
#pragma unroll
        for (int j = 0; j < 5; j++) {
            wmma::fragment<wmma::matrix_b, 16, 16, 16, __half, wmma::row_major> bf;
            wmma::load_matrix_sync(bf, &Bs[k * LDB2 + j * 16], LDB2);
            wmma::mma_sync(acc[j], af, bf, acc[j]);
        }
    }
    __syncthreads();
#pragma unroll
    for (int j = 0; j < 5; j++)
        wmma::store_matrix_sync(&Cs[wr * LDB2 + j * 16], acc[j], LDB2,
                                wmma::mem_row_major);
    __syncthreads();

    // coalesced epilogue
    for (int c = tid; c < 640; c += 256) {            // y2h: 5 uint4/row
        int row = c / 5, ci = c % 5;
        int m = node0 + row;
        if (m < n) {
            const float* cp = &Cs[row * LDB2 + ci * 8];
            __half2 h0 = __floats2half2_rn(cp[0], cp[1]);
            __half2 h1 = __floats2half2_rn(cp[2], cp[3]);
            __half2 h2 = __floats2half2_rn(cp[4], cp[5]);
            __half2 h3 = __floats2half2_rn(cp[6], cp[7]);
            uint4 u;
            u.x = *reinterpret_cast<uint32_t*>(&h0);
            u.y = *reinterpret_cast<uint32_t*>(&h1);
            u.z = *reinterpret_cast<uint32_t*>(&h2);
            u.w = *reinterpret_cast<uint32_t*>(&h3);
            ((uint4*)(g_y2h + (size_t)m * 40))[ci] = u;
        }
    }
    for (int c = tid; c < 1280; c += 256) {           // r2: 10 float4/row
        int row = c / 10, ci = c % 10;
        int m = node0 + row;
        if (m < n) {
            const float* cp = &Cs[row * LDB2 + 40 + ci * 4];
            float4 v = make_float4(cp[0] + bl[ci * 4], cp[1] + bl[ci * 4 + 1],
                                   cp[2] + bl[ci * 4 + 2], cp[3] + bl[ci * 4 + 3]);
            ((float4*)(g_r2 + (size_t)m * 40))[ci] = v;
        }
    }
}

// ------- combine layer 2: out = log_softmax(gather_mean(y2) + r2), MLP 4 -
__global__ void combine2_kernel(float* __restrict__ out, int n) {
    int node = (blockIdx.x * blockDim.x + threadIdx.x) >> 5;
    int lane = threadIdx.x & 31;
    if (node >= n) return;
    int s = g_rowstart[node];
    int dg = g_deg[node];
    int e = s + dg;
    float inv = 1.f / (float)max(dg, 1);
    const __half2* y2 = (const __half2*)g_y2h;
    bool act = lane < 20;
    float a0 = 0.f, a1 = 0.f, b0 = 0.f, b1 = 0.f;
    float c0 = 0.f, c1 = 0.f, d0 = 0.f, d1 = 0.f;
    for (int base = s; base < e; base += 32) {
        int cnt = min(32, e - base);
        int idx = (lane < cnt) ? g_ebuf[base + lane] : 0;
        int j = 0;
        for (; j + 4 <= cnt; j += 4) {
            int n0 = __shfl_sync(0xffffffffu, idx, j);
            int n1 = __shfl_sync(0xffffffffu, idx, j + 1);
            int n2 = __shfl_sync(0xffffffffu, idx, j + 2);
            int n3 = __shfl_sync(0xffffffffu, idx, j + 3);
            if (act) {
                float2 v0 = __half22float2(y2[n0 * 20 + lane]);
                float2 v1 = __half22float2(y2[n1 * 20 + lane]);
                float2 v2 = __half22float2(y2[n2 * 20 + lane]);
                float2 v3 = __half22float2(y2[n3 * 20 + lane]);
                a0 += v0.x; a1 += v0.y;
                b0 += v1.x; b1 += v1.y;
                c0 += v2.x; c1 += v2.y;
                d0 += v3.x; d1 += v3.y;
            }
        }
        for (; j < cnt; j++) {
            int n0 = __shfl_sync(0xffffffffu, idx, j);
            if (act) {
                float2 v0 = __half22float2(y2[n0 * 20 + lane]);
                a0 += v0.x; a1 += v0.y;
            }
        }
    }
    a0 += b0 + c0 + d0;
    a1 += b1 + c1 + d1;
    const float NEG_INF = __int_as_float(0xff800000);
    float v0 = NEG_INF, v1 = NEG_INF;
    if (act) {
        v0 = a0 * inv + g_r2[node * 40 + 2 * lane];
        v1 = a1 * inv + g_r2[node * 40 + 2 * lane + 1];
    }
    float m = fmaxf(v0, v1);
#pragma unroll
    for (int o = 16; o > 0; o >>= 1) m = fmaxf(m, __shfl_xor_sync(0xffffffffu, m, o));
    float sum = act ? (expf(v0 - m) + expf(v1 - m)) : 0.f;
#pragma unroll
    for (int o = 16; o > 0; o >>= 1) sum += __shfl_xor_sync(0xffffffffu, sum, o);
    float lse = logf(sum);
    if (act) {
        out[node * 40 + 2 * lane] = v0 - m - lse;
        out[node * 40 + 2 * lane + 1] = v1 - m - lse;
    }
}

// ---------------- launch ----------------
extern "C" void kernel_launch(void* const* d_in, const int* in_sizes, int n_in,
                              void* d_out, int out_size) {
    const float* x   = (const float*)d_in[0];
    const int*   ei  = (const int*)d_in[1];   // int64 inputs delivered as int32
    const float* Wl1 = (const float*)d_in[2];
    const float* bl1 = (const float*)d_in[3];
    const float* Wr1 = (const float*)d_in[4];
    const float* Wl2 = (const float*)d_in[5];
    const float* bl2 = (const float*)d_in[6];
    const float* Wr2 = (const float*)d_in[7];
    float* out = (float*)d_out;

    int n = in_sizes[0] / 128;
    int e = in_sizes[1] / 2;
    const int* src = ei;
    const int* dst = ei + e;

    const int SMEM1 = 128 * LDA1 * 2 * 2;   // 69632 B (A + B; C alias fits)
    const int SMEM2 = 128 * LDB2 * 4;       // 45056 B (C alias is max)
    cudaFuncSetAttribute(gemm1_kernel, cudaFuncAttributeMaxDynamicSharedMemorySize, SMEM1);
    cudaFuncSetAttribute(gemm2_kernel, cudaFuncAttributeMaxDynamicSharedMemorySize, SMEM2);

    void* deg_ptr = nullptr;
    cudaGetSymbolAddress(&deg_ptr, g_deg);

    cudaStream_t s2;
    cudaStreamCreateWithFlags(&s2, cudaStreamNonBlocking);
    cudaEvent_t evFork, evJoin;
    cudaEventCreateWithFlags(&evFork, cudaEventDisableTiming);
    cudaEventCreateWithFlags(&evJoin, cudaEventDisableTiming);

    cudaEventRecord(evFork, 0);
    cudaStreamWaitEvent(s2, evFork, 0);

    cudaMemsetAsync(deg_ptr, 0, (size_t)n * sizeof(int), s2);
    count_deg_kernel<<<(e + 255) / 256, 256, 0, s2>>>(dst, e);
    assign_kernel<<<(n + 255) / 256, 256, 0, s2>>>(n);
    fill_csr_kernel<<<(e + 255) / 256, 256, 0, s2>>>(src, dst, e);
    cudaEventRecord(evJoin, s2);

    int nblk = (n + 127) / 128;
    gemm1_kernel<<<nblk, 512, SMEM1>>>(x, Wl1, Wr1, bl1, n);

    cudaStreamWaitEvent(0, evJoin, 0);
    combine1_kernel<<<(n * 32 + 255) / 256, 256>>>(n);
    gemm2_kernel<<<nblk, 256, SMEM2>>>(Wl2, Wr2, bl2, n);
    combine2_kernel<<<(n * 32 + 255) / 256, 256>>>(out, n);
}